// round 11
// baseline (speedup 1.0000x reference)
#include <cuda_runtime.h>

// SpinorBilinears: psi [B=8, N=65536, S=4] f32, gamma [C=8, 4, 4] f32.
// Outputs flat in d_out: K0 [BN] | K1 [BN,8,8] | K2 [BN,8,8]
//   u_c = gamma_c^T p,  v_c = gamma_c p
//   K1[c][d] = 0.5*(u_c.v_d - u_d.v_c),  K2[c][d] = 0.5*(u_c.v_d + u_d.v_c)
//
// R9 winner (swizzled block staging + __stcs streaming stores), re-shaped for
// latency hiding: TPB=64, 96-reg cap -> 10 blocks/SM (20 warps), and each
// __syncthreads spans only 2 warps. 10 independent store pipelines per SM.

#define TPB 64   // tokens per block == threads per block

__device__ __forceinline__ float dot4(const float* a, const float* b) {
    return fmaf(a[0], b[0], fmaf(a[1], b[1], fmaf(a[2], b[2], a[3] * b[3])));
}

__global__ __launch_bounds__(TPB, 10) void spinor_bilinears_kernel(
    const float4* __restrict__ psi4,
    const float4* __restrict__ gamma4,
    float* __restrict__ out,
    int BN)
{
    __shared__ float4 sg[32];            // gamma: 8 matrices x 4 rows, as float4
    __shared__ float  stage[TPB * 64];   // 16 KB staging: [64 tokens x 64 floats]

    const int tid = threadIdx.x;
    if (tid < 32) sg[tid] = __ldg(gamma4 + tid);
    __syncthreads();

    const int t = blockIdx.x * TPB + tid;   // token id; grid sized exactly BN/TPB

    // ---- load spinor (16B aligned, coalesced) ----
    const float4 p4 = __ldg(psi4 + t);
    const float p[4] = {p4.x, p4.y, p4.z, p4.w};

    // ---- K0 (coalesced streaming STG.32) ----
    __stcs(out + t, dot4(p, p));

    // ---- u_c = gamma_c^T p ; v_c = gamma_c p ----
    float u[8][4], v[8][4];
#pragma unroll
    for (int c = 0; c < 8; c++) {
        const float4 r0 = sg[c * 4 + 0];
        const float4 r1 = sg[c * 4 + 1];
        const float4 r2 = sg[c * 4 + 2];
        const float4 r3 = sg[c * 4 + 3];
        v[c][0] = fmaf(r0.x, p[0], fmaf(r0.y, p[1], fmaf(r0.z, p[2], r0.w * p[3])));
        v[c][1] = fmaf(r1.x, p[0], fmaf(r1.y, p[1], fmaf(r1.z, p[2], r1.w * p[3])));
        v[c][2] = fmaf(r2.x, p[0], fmaf(r2.y, p[1], fmaf(r2.z, p[2], r2.w * p[3])));
        v[c][3] = fmaf(r3.x, p[0], fmaf(r3.y, p[1], fmaf(r3.z, p[2], r3.w * p[3])));
        u[c][0] = fmaf(r0.x, p[0], fmaf(r1.x, p[1], fmaf(r2.x, p[2], r3.x * p[3])));
        u[c][1] = fmaf(r0.y, p[0], fmaf(r1.y, p[1], fmaf(r2.y, p[2], r3.y * p[3])));
        u[c][2] = fmaf(r0.z, p[0], fmaf(r1.z, p[1], fmaf(r2.z, p[2], r3.z * p[3])));
        u[c][3] = fmaf(r0.w, p[0], fmaf(r1.w, p[1], fmaf(r2.w, p[2], r3.w * p[3])));
    }

    const size_t bn      = (size_t)BN;
    const size_t blkBase = (size_t)blockIdx.x * (size_t)(TPB * 64);
    const int    sw      = tid & 15;     // float4-granular XOR swizzle key

    // ================= K1 (antisymmetric) =================
#pragma unroll
    for (int c = 0; c < 8; c++) {
#pragma unroll
        for (int d4 = 0; d4 < 2; d4++) {
            float4 row;
            {
                const int d = d4 * 4;
                row.x = 0.5f * (dot4(u[c], v[d + 0]) - dot4(u[d + 0], v[c]));
                row.y = 0.5f * (dot4(u[c], v[d + 1]) - dot4(u[d + 1], v[c]));
                row.z = 0.5f * (dot4(u[c], v[d + 2]) - dot4(u[d + 2], v[c]));
                row.w = 0.5f * (dot4(u[c], v[d + 3]) - dot4(u[d + 3], v[c]));
            }
            const int e4 = c * 2 + d4;                              // 0..15
            *reinterpret_cast<float4*>(&stage[tid * 64 + ((e4 ^ sw) << 2)]) = row;
        }
    }
    __syncthreads();

    {
        float* __restrict__ dst = out + bn + blkBase;
#pragma unroll
        for (int it = 0; it < 16; it++) {
            const int o   = it * (TPB * 4) + tid * 4;   // float offset in block's 4096-float region
            const int tok = o >> 6;
            const int e4  = (o >> 2) & 15;
            const float4 val =
                *reinterpret_cast<const float4*>(&stage[tok * 64 + ((e4 ^ (tok & 15)) << 2)]);
            __stcs(reinterpret_cast<float4*>(&dst[o]), val);
        }
    }
    __syncthreads();

    // ================= K2 (symmetric) =================
#pragma unroll
    for (int c = 0; c < 8; c++) {
#pragma unroll
        for (int d4 = 0; d4 < 2; d4++) {
            float4 row;
            {
                const int d = d4 * 4;
                row.x = 0.5f * (dot4(u[c], v[d + 0]) + dot4(u[d + 0], v[c]));
                row.y = 0.5f * (dot4(u[c], v[d + 1]) + dot4(u[d + 1], v[c]));
                row.z = 0.5f * (dot4(u[c], v[d + 2]) + dot4(u[d + 2], v[c]));
                row.w = 0.5f * (dot4(u[c], v[d + 3]) + dot4(u[d + 3], v[c]));
            }
            const int e4 = c * 2 + d4;
            *reinterpret_cast<float4*>(&stage[tid * 64 + ((e4 ^ sw) << 2)]) = row;
        }
    }
    __syncthreads();

    {
        float* __restrict__ dst = out + bn + bn * 64 + blkBase;
#pragma unroll
        for (int it = 0; it < 16; it++) {
            const int o   = it * (TPB * 4) + tid * 4;
            const int tok = o >> 6;
            const int e4  = (o >> 2) & 15;
            const float4 val =
                *reinterpret_cast<const float4*>(&stage[tok * 64 + ((e4 ^ (tok & 15)) << 2)]);
            __stcs(reinterpret_cast<float4*>(&dst[o]), val);
        }
    }
}

extern "C" void kernel_launch(void* const* d_in, const int* in_sizes, int n_in,
                              void* d_out, int out_size) {
    const float4* psi4   = (const float4*)d_in[0];   // [B, N, 4] f32
    const float4* gamma4 = (const float4*)d_in[1];   // [8, 4, 4] f32
    float* out = (float*)d_out;

    const int BN = in_sizes[0] / 4;                  // 524288 tokens
    const int grid = BN / TPB;                       // 8192, exact

    spinor_bilinears_kernel<<<grid, TPB>>>(psi4, gamma4, out, BN);
}

// round 12
// speedup vs baseline: 1.1328x; 1.1328x over previous
#include <cuda_runtime.h>

// SpinorBilinears: psi [B=8, N=65536, S=4] f32, gamma [C=8, 4, 4] f32.
// Outputs flat in d_out: K0 [BN] | K1 [BN,8,8] | K2 [BN,8,8]
//   u_c = gamma_c^T p,  v_c = gamma_c p
//   K1[c][d] = 0.5*(u_c.v_d - u_d.v_c),  K2[c][d] = 0.5*(u_c.v_d + u_d.v_c)
//
// R9 winner (smem gamma + swizzled staging + __stcs streaming stores) with
// warp-private 8KB staging slices: only __syncwarp in the hot path, warps
// drain stores independently. __launch_bounds__(128,5) -> ~102 regs,
// 5 blocks/SM (20 warps).

#define TPB 128

__device__ __forceinline__ float dot4(const float* a, const float* b) {
    return fmaf(a[0], b[0], fmaf(a[1], b[1], fmaf(a[2], b[2], a[3] * b[3])));
}

__device__ __forceinline__ int swz(int e4, int l) {   // float4-index swizzle
    return (e4 & 8) | ((e4 & 7) ^ (l & 7));
}

__global__ __launch_bounds__(TPB, 5) void spinor_bilinears_kernel(
    const float4* __restrict__ psi4,
    const float4* __restrict__ gamma4,
    float* __restrict__ out,
    int BN)
{
    __shared__ float4 sg[32];             // gamma: 8 matrices x 4 rows
    __shared__ float4 stage4[4][512];     // 8 KB per warp

    const int tid  = threadIdx.x;
    const int warp = tid >> 5;
    const int l    = tid & 31;

    if (tid < 32) sg[tid] = __ldg(gamma4 + tid);
    __syncthreads();                      // once, before the hot path

    const int t = blockIdx.x * TPB + tid; // token id; grid exact

    const float4 p4 = __ldg(psi4 + t);
    const float p[4] = {p4.x, p4.y, p4.z, p4.w};

    // K0 (coalesced streaming STG.32)
    __stcs(out + t, dot4(p, p));

    // u_c = gamma_c^T p ; v_c = gamma_c p  (broadcast LDS, 1 wavefront each)
    float u[8][4], v[8][4];
#pragma unroll
    for (int c = 0; c < 8; c++) {
        const float4 r0 = sg[c * 4 + 0];
        const float4 r1 = sg[c * 4 + 1];
        const float4 r2 = sg[c * 4 + 2];
        const float4 r3 = sg[c * 4 + 3];
        v[c][0] = fmaf(r0.x, p[0], fmaf(r0.y, p[1], fmaf(r0.z, p[2], r0.w * p[3])));
        v[c][1] = fmaf(r1.x, p[0], fmaf(r1.y, p[1], fmaf(r1.z, p[2], r1.w * p[3])));
        v[c][2] = fmaf(r2.x, p[0], fmaf(r2.y, p[1], fmaf(r2.z, p[2], r2.w * p[3])));
        v[c][3] = fmaf(r3.x, p[0], fmaf(r3.y, p[1], fmaf(r3.z, p[2], r3.w * p[3])));
        u[c][0] = fmaf(r0.x, p[0], fmaf(r1.x, p[1], fmaf(r2.x, p[2], r3.x * p[3])));
        u[c][1] = fmaf(r0.y, p[0], fmaf(r1.y, p[1], fmaf(r2.y, p[2], r3.y * p[3])));
        u[c][2] = fmaf(r0.z, p[0], fmaf(r1.z, p[1], fmaf(r2.z, p[2], r3.z * p[3])));
        u[c][3] = fmaf(r0.w, p[0], fmaf(r1.w, p[1], fmaf(r2.w, p[2], r3.w * p[3])));
    }

    const size_t bn = (size_t)BN;
    const int    t0 = blockIdx.x * TPB + warp * 32;   // warp's first token
    float4* __restrict__ k1dst = reinterpret_cast<float4*>(out + bn) + (size_t)t0 * 16;
    float4* __restrict__ k2dst = reinterpret_cast<float4*>(out + bn + bn * 64) + (size_t)t0 * 16;

    // ================= K1 (antisymmetric) =================
#pragma unroll
    for (int c = 0; c < 8; c++) {
#pragma unroll
        for (int d4 = 0; d4 < 2; d4++) {
            const int d = d4 * 4;
            float4 r;
            r.x = 0.5f * (dot4(u[c], v[d + 0]) - dot4(u[d + 0], v[c]));
            r.y = 0.5f * (dot4(u[c], v[d + 1]) - dot4(u[d + 1], v[c]));
            r.z = 0.5f * (dot4(u[c], v[d + 2]) - dot4(u[d + 2], v[c]));
            r.w = 0.5f * (dot4(u[c], v[d + 3]) - dot4(u[d + 3], v[c]));
            stage4[warp][l * 16 + swz(c * 2 + d4, l)] = r;
        }
    }
    __syncwarp();
#pragma unroll
    for (int i = 0; i < 16; i++) {
        const int f4  = i * 32 + l;
        const int tok = f4 >> 4;
        const int e4  = f4 & 15;
        __stcs(&k1dst[f4], stage4[warp][tok * 16 + swz(e4, tok)]);
    }
    __syncwarp();

    // ================= K2 (symmetric) =================
#pragma unroll
    for (int c = 0; c < 8; c++) {
#pragma unroll
        for (int d4 = 0; d4 < 2; d4++) {
            const int d = d4 * 4;
            float4 r;
            r.x = 0.5f * (dot4(u[c], v[d + 0]) + dot4(u[d + 0], v[c]));
            r.y = 0.5f * (dot4(u[c], v[d + 1]) + dot4(u[d + 1], v[c]));
            r.z = 0.5f * (dot4(u[c], v[d + 2]) + dot4(u[d + 2], v[c]));
            r.w = 0.5f * (dot4(u[c], v[d + 3]) + dot4(u[d + 3], v[c]));
            stage4[warp][l * 16 + swz(c * 2 + d4, l)] = r;
        }
    }
    __syncwarp();
#pragma unroll
    for (int i = 0; i < 16; i++) {
        const int f4  = i * 32 + l;
        const int tok = f4 >> 4;
        const int e4  = f4 & 15;
        __stcs(&k2dst[f4], stage4[warp][tok * 16 + swz(e4, tok)]);
    }
}

extern "C" void kernel_launch(void* const* d_in, const int* in_sizes, int n_in,
                              void* d_out, int out_size) {
    const float4* psi4   = (const float4*)d_in[0];   // [B, N, 4] f32
    const float4* gamma4 = (const float4*)d_in[1];   // [8, 4, 4] f32
    float* out = (float*)d_out;

    const int BN = in_sizes[0] / 4;                  // 524288 tokens
    const int grid = BN / TPB;                       // 4096, exact

    spinor_bilinears_kernel<<<grid, TPB>>>(psi4, gamma4, out, BN);
}